// round 17
// baseline (speedup 1.0000x reference)
#include <cuda_runtime.h>
#include <cuda_fp16.h>
#include <cstdint>

#define THREADS 256
#define N_TOK   64
#define DIM     96
#define HEADS   6

#define PITCHB  208u      // bytes per smem row (104 fp16; 13*16B, conflict-free LDSM)
#define PLANE   13312u    // one 64-row fp16 plane
#define WB1     53248u    // window-1 base (4 planes per window)
#define LOG2E   1.44269504088896f

// per-window plane offsets: XP=wb+0 (x staging, later O), QP=wb+PLANE, KP=wb+2*PLANE, VP=wb+3*PLANE
#define SMEM_BYTES 106496u   // 2 windows * 4 planes; 2 CTAs/SM (208KB <= 228KB)

// ---- prepped globals (all in mma-fragment order) ----
// q weights pre-scaled by 0.25*log2e; bias/mask tables pre-scaled by log2e.
__device__ uint4 g_qwf4[3456];            // qkv W: 3 slices * 6 kt * 6 np * 32 lanes
__device__ uint4 g_pwf4[1152];            // proj W: 6 kt * 6 np * 32 lanes
__device__ uint2 g_biasf[HEADS * 4 * 8 * 32];   // [(h*4+mt)*8+nt][lane]
__device__ uint2 g_maskf[512 * 4 * 8 * 32];     // [(w*4+mt)*8+nt][lane]

__device__ __forceinline__ uint32_t packh(float a, float b) {
    __half2 v = __floats2half2_rn(a, b);
    return *reinterpret_cast<uint32_t*>(&v);
}
__device__ __forceinline__ float ex2f(float v) {
    float r;
    asm("ex2.approx.f32 %0, %1;" : "=f"(r) : "f"(v));
    return r;
}

__global__ void __launch_bounds__(256)
prep_kernel(const float* __restrict__ qkv_w, const float* __restrict__ proj_w,
            const float* __restrict__ rpb, const int* __restrict__ ridx,
            const float* __restrict__ mask, int nW)
{
    int idx = blockIdx.x * 256 + threadIdx.x;
    if (idx < 3456) {
        int lane = idx & 31, np = (idx >> 5) % 6, kt = (idx / 192) % 6, s = idx / 1152;
        int k0 = kt * 16 + (lane & 3) * 2;
        int nc0 = (2 * np) * 8 + (lane >> 2);
        int nc1 = nc0 + 8;
        const float scl = (s == 0) ? 0.25f * LOG2E : 1.0f;
        const float* w0 = qkv_w + s * 96 + nc0;
        const float* w1 = qkv_w + s * 96 + nc1;
        uint4 r;
        r.x = packh(w0[(k0)     * 288] * scl, w0[(k0 + 1) * 288] * scl);
        r.y = packh(w0[(k0 + 8) * 288] * scl, w0[(k0 + 9) * 288] * scl);
        r.z = packh(w1[(k0)     * 288] * scl, w1[(k0 + 1) * 288] * scl);
        r.w = packh(w1[(k0 + 8) * 288] * scl, w1[(k0 + 9) * 288] * scl);
        g_qwf4[idx] = r;
    } else if (idx < 4608) {
        int j = idx - 3456;
        int lane = j & 31, np = (j >> 5) % 6, kt = j / 192;
        int k0 = kt * 16 + (lane & 3) * 2;
        int nc0 = (2 * np) * 8 + (lane >> 2);
        int nc1 = nc0 + 8;
        const float* w0 = proj_w + nc0;
        const float* w1 = proj_w + nc1;
        uint4 r;
        r.x = packh(w0[(k0)     * 96], w0[(k0 + 1) * 96]);
        r.y = packh(w0[(k0 + 8) * 96], w0[(k0 + 9) * 96]);
        r.z = packh(w1[(k0)     * 96], w1[(k0 + 1) * 96]);
        r.w = packh(w1[(k0 + 8) * 96], w1[(k0 + 9) * 96]);
        g_pwf4[j] = r;
    } else if (idx < 4608 + 6144) {
        int j = idx - 4608;
        int lane = j & 31, nt = (j >> 5) & 7, mt = (j >> 8) & 3, h = j >> 10;
        int r0 = mt * 16 + (lane >> 2);
        int c0 = nt * 8 + (lane & 3) * 2;
        float b00 = rpb[ridx[(r0)     * 64 + c0]     * HEADS + h] * LOG2E;
        float b01 = rpb[ridx[(r0)     * 64 + c0 + 1] * HEADS + h] * LOG2E;
        float b10 = rpb[ridx[(r0 + 8) * 64 + c0]     * HEADS + h] * LOG2E;
        float b11 = rpb[ridx[(r0 + 8) * 64 + c0 + 1] * HEADS + h] * LOG2E;
        uint2 r;
        r.x = packh(b00, b01);
        r.y = packh(b10, b11);
        g_biasf[j] = r;
    } else {
        int j = idx - (4608 + 6144);
        if (j < nW * 1024) {
            int lane = j & 31, nt = (j >> 5) & 7, mt = (j >> 8) & 3, w = j >> 10;
            int r0 = mt * 16 + (lane >> 2);
            int c0 = nt * 8 + (lane & 3) * 2;
            const float* mb = mask + (size_t)w * 4096;
            float2 a = *(const float2*)(mb + (size_t)r0 * 64 + c0);
            float2 c = *(const float2*)(mb + (size_t)(r0 + 8) * 64 + c0);
            uint2 r;
            r.x = packh(a.x * LOG2E, a.y * LOG2E);
            r.y = packh(c.x * LOG2E, c.y * LOG2E);
            g_maskf[j] = r;
        }
    }
}

// ---- PTX helpers ----
__device__ __forceinline__ uint32_t smem_u32(const void* p) {
    uint32_t a;
    asm("{ .reg .u64 t; cvta.to.shared.u64 t, %1; cvt.u32.u64 %0, t; }" : "=r"(a) : "l"(p));
    return a;
}
__device__ __forceinline__ void ldsm_x4(uint32_t* r, uint32_t a) {
    asm volatile("ldmatrix.sync.aligned.m8n8.x4.shared.b16 {%0,%1,%2,%3}, [%4];"
        : "=r"(r[0]), "=r"(r[1]), "=r"(r[2]), "=r"(r[3]) : "r"(a));
}
__device__ __forceinline__ void ldsm_x4t(uint32_t* r, uint32_t a) {
    asm volatile("ldmatrix.sync.aligned.m8n8.x4.trans.shared.b16 {%0,%1,%2,%3}, [%4];"
        : "=r"(r[0]), "=r"(r[1]), "=r"(r[2]), "=r"(r[3]) : "r"(a));
}
__device__ __forceinline__ void mma_h(float* c, const uint32_t* a,
                                      uint32_t b0, uint32_t b1) {
    asm volatile("mma.sync.aligned.m16n8k16.row.col.f32.f16.f16.f32 "
        "{%0,%1,%2,%3}, {%4,%5,%6,%7}, {%8,%9}, {%0,%1,%2,%3};"
        : "+f"(c[0]), "+f"(c[1]), "+f"(c[2]), "+f"(c[3])
        : "r"(a[0]), "r"(a[1]), "r"(a[2]), "r"(a[3]), "r"(b0), "r"(b1));
}

extern __shared__ char smc[];

__global__ void __launch_bounds__(THREADS, 2)
win_attn_mma(const float* __restrict__ x,
             const float* __restrict__ qkv_b,
             const float* __restrict__ proj_b,
             float* __restrict__ out,
             int nW)
{
    const int t = threadIdx.x, wid = t >> 5, lane = t & 31, b2 = blockIdx.x;
    const uint32_t sb = smem_u32(smc);
    const int mt = wid & 3;      // m tile 0..3
    const int g6 = wid >> 2;     // n group 0..1 -> heads 3*g6..3*g6+2

    // ---- stage x for BOTH windows: coalesced LDG.128 -> packed fp16 XP planes ----
    {
        const float4* xb4 = (const float4*)(x + (size_t)b2 * 12288);
        #pragma unroll
        for (int i = 0; i < 12; i++) {
            int e4 = t + i * THREADS;            // 3072 float4
            int grow = e4 / 24, c4 = e4 % 24;    // grow 0..127
            int w = grow >> 6, r = grow & 63;
            float4 v = xb4[e4];
            uint2 p;
            p.x = packh(v.x, v.y);
            p.y = packh(v.z, v.w);
            *(uint2*)(smc + (w ? WB1 : 0u) + (uint32_t)r * PITCHB + c4 * 8) = p;
        }
    }
    __syncthreads();

    // ---- load A fragments for both windows (held across all 3 slices) ----
    uint32_t xah[2][6][4];
    #pragma unroll
    for (int w = 0; w < 2; w++) {
        uint32_t base = sb + (w ? WB1 : 0u);
        #pragma unroll
        for (int kt = 0; kt < 6; kt++) {
            uint32_t ar = (uint32_t)(mt * 16 + (lane & 15)) * PITCHB
                        + (uint32_t)(kt * 16 + ((lane >> 4) << 3)) * 2;
            ldsm_x4(xah[w][kt], base + ar);
        }
    }
    const int r0 = mt * 16 + (lane >> 2);

    // ---- qkv GEMM: 3 slices; one weight load feeds BOTH windows ----
    #pragma unroll 1
    for (int s = 0; s < 3; s++) {
        float acc[2][6][4];
        #pragma unroll
        for (int w = 0; w < 2; w++)
            #pragma unroll
            for (int j = 0; j < 6; j++)
                { acc[w][j][0] = 0.f; acc[w][j][1] = 0.f; acc[w][j][2] = 0.f; acc[w][j][3] = 0.f; }
        #pragma unroll
        for (int kt = 0; kt < 6; kt++) {
            #pragma unroll
            for (int jp = 0; jp < 3; jp++) {
                int fi = ((s * 6 + kt) * 6 + g6 * 3 + jp) * 32 + lane;
                uint4 wreg = g_qwf4[fi];
                mma_h(acc[0][2*jp],   xah[0][kt], wreg.x, wreg.y);
                mma_h(acc[0][2*jp+1], xah[0][kt], wreg.z, wreg.w);
                mma_h(acc[1][2*jp],   xah[1][kt], wreg.x, wreg.y);
                mma_h(acc[1][2*jp+1], xah[1][kt], wreg.z, wreg.w);
            }
        }
        // epilogue: +bias (scaled for q), pack -> Q/K/V plane of each window
        const float bscl = (s == 0) ? 0.25f * LOG2E : 1.0f;
        const uint32_t pofs = (s + 1) * PLANE;   // QP / KP / VP offset within window
        #pragma unroll
        for (int j = 0; j < 6; j++) {
            int c0 = (g6 * 6 + j) * 8 + (lane & 3) * 2;
            float b0 = __ldg(qkv_b + s * 96 + c0)     * bscl;
            float b1 = __ldg(qkv_b + s * 96 + c0 + 1) * bscl;
            uint32_t off = pofs + (uint32_t)r0 * PITCHB + c0 * 2;
            #pragma unroll
            for (int w = 0; w < 2; w++) {
                uint32_t wb = w ? WB1 : 0u;
                *(uint32_t*)(smc + wb + off) =
                    packh(acc[w][j][0] + b0, acc[w][j][1] + b1);
                *(uint32_t*)(smc + wb + off + 8 * PITCHB) =
                    packh(acc[w][j][2] + b0, acc[w][j][3] + b1);
            }
        }
    }
    __syncthreads();   // q/k/v complete for both windows

    // ---- preload mask fragments for both windows ----
    uint2 mreg[2][8];
    #pragma unroll
    for (int w = 0; w < 2; w++) {
        const uint2* mfp = g_maskf + ((size_t)((2 * b2 + w) % nW) * 4 + mt) * 256 + lane;
        #pragma unroll
        for (int nt = 0; nt < 8; nt++) mreg[w][nt] = mfp[nt * 32];
    }

    // ---- attention: 3 head-units x 2 windows; bias loaded once per unit ----
    #pragma unroll 1
    for (int iu = 0; iu < 3; iu++) {
        const int h = 3 * g6 + iu;
        uint2 breg[8];
        {
            const uint2* bfp = g_biasf + ((size_t)h * 4 + mt) * 256 + lane;
            #pragma unroll
            for (int nt = 0; nt < 8; nt++) breg[nt] = bfp[nt * 32];
        }
        #pragma unroll 1
        for (int w = 0; w < 2; w++) {
            const uint32_t wb = w ? WB1 : 0u;
            uint32_t qhf[4];
            {
                uint32_t ar = (uint32_t)(mt * 16 + (lane & 15)) * PITCHB
                            + (uint32_t)(h * 16 + ((lane >> 4) << 3)) * 2;
                ldsm_x4(qhf, sb + wb + PLANE + ar);
            }
            float s8[8][4];
            #pragma unroll
            for (int ntp = 0; ntp < 4; ntp++) {
                uint32_t kh[4];
                uint32_t br = (uint32_t)(ntp * 16 + (lane & 15)) * PITCHB
                            + (uint32_t)(h * 16 + ((lane >> 4) << 3)) * 2;
                ldsm_x4(kh, sb + wb + 2 * PLANE + br);
                #pragma unroll
                for (int half = 0; half < 2; half++) {
                    int nt = 2 * ntp + half;
                    s8[nt][0] = 0.f; s8[nt][1] = 0.f; s8[nt][2] = 0.f; s8[nt][3] = 0.f;
                    mma_h(s8[nt], qhf, kh[half], kh[half + 2]);
                }
            }
            // + (bias + mask) in log2 domain; bare ex2
            float sum0 = 0.f, sum1 = 0.f;
            #pragma unroll
            for (int nt = 0; nt < 8; nt++) {
                __half2 a0 = __hadd2(*reinterpret_cast<__half2*>(&breg[nt].x),
                                     *reinterpret_cast<__half2*>(&mreg[w][nt].x));
                __half2 a1 = __hadd2(*reinterpret_cast<__half2*>(&breg[nt].y),
                                     *reinterpret_cast<__half2*>(&mreg[w][nt].y));
                float2 f0 = __half22float2(a0);
                float2 f1 = __half22float2(a1);
                s8[nt][0] = ex2f(s8[nt][0] + f0.x); sum0 += s8[nt][0];
                s8[nt][1] = ex2f(s8[nt][1] + f0.y); sum0 += s8[nt][1];
                s8[nt][2] = ex2f(s8[nt][2] + f1.x); sum1 += s8[nt][2];
                s8[nt][3] = ex2f(s8[nt][3] + f1.y); sum1 += s8[nt][3];
            }
            sum0 += __shfl_xor_sync(0xffffffffu, sum0, 1);
            sum0 += __shfl_xor_sync(0xffffffffu, sum0, 2);
            sum1 += __shfl_xor_sync(0xffffffffu, sum1, 1);
            sum1 += __shfl_xor_sync(0xffffffffu, sum1, 2);
            float inv0 = 1.f / sum0, inv1 = 1.f / sum1;

            // PV with unnormalized P
            float o[2][4];
            o[0][0]=0.f;o[0][1]=0.f;o[0][2]=0.f;o[0][3]=0.f;
            o[1][0]=0.f;o[1][1]=0.f;o[1][2]=0.f;o[1][3]=0.f;
            #pragma unroll
            for (int kt = 0; kt < 4; kt++) {
                uint32_t pa[4];
                pa[0] = packh(s8[2*kt][0],   s8[2*kt][1]);
                pa[1] = packh(s8[2*kt][2],   s8[2*kt][3]);
                pa[2] = packh(s8[2*kt+1][0], s8[2*kt+1][1]);
                pa[3] = packh(s8[2*kt+1][2], s8[2*kt+1][3]);
                uint32_t vr = (uint32_t)(kt * 16 + (lane & 15)) * PITCHB
                            + (uint32_t)(h * 16 + ((lane >> 4) << 3)) * 2;
                uint32_t vh[4];
                ldsm_x4t(vh, sb + wb + 3 * PLANE + vr);
                mma_h(o[0], pa, vh[0], vh[1]);
                mma_h(o[1], pa, vh[2], vh[3]);
            }
            // normalize, pack, store O into XP plane
            #pragma unroll
            for (int nt2 = 0; nt2 < 2; nt2++) {
                int c0 = h * 16 + nt2 * 8 + (lane & 3) * 2;
                uint32_t off = (uint32_t)r0 * PITCHB + c0 * 2;
                *(uint32_t*)(smc + wb + off) =
                    packh(o[nt2][0] * inv0, o[nt2][1] * inv0);
                *(uint32_t*)(smc + wb + off + 8 * PITCHB) =
                    packh(o[nt2][2] * inv1, o[nt2][3] * inv1);
            }
        }
    }
    __syncthreads();   // O complete in XP planes; Q/K/V dead

    // ---- proj GEMM: one weight load feeds both windows ----
    {
        float acc[2][6][4];
        #pragma unroll
        for (int w = 0; w < 2; w++)
            #pragma unroll
            for (int j = 0; j < 6; j++)
                { acc[w][j][0] = 0.f; acc[w][j][1] = 0.f; acc[w][j][2] = 0.f; acc[w][j][3] = 0.f; }
        #pragma unroll
        for (int kt = 0; kt < 6; kt++) {
            uint32_t ah0[4], ah1[4];
            uint32_t ar = (uint32_t)(mt * 16 + (lane & 15)) * PITCHB
                        + (uint32_t)(kt * 16 + ((lane >> 4) << 3)) * 2;
            ldsm_x4(ah0, sb + ar);
            ldsm_x4(ah1, sb + WB1 + ar);
            #pragma unroll
            for (int jp = 0; jp < 3; jp++) {
                int fi = (kt * 6 + g6 * 3 + jp) * 32 + lane;
                uint4 wreg = g_pwf4[fi];
                mma_h(acc[0][2*jp],   ah0, wreg.x, wreg.y);
                mma_h(acc[0][2*jp+1], ah0, wreg.z, wreg.w);
                mma_h(acc[1][2*jp],   ah1, wreg.x, wreg.y);
                mma_h(acc[1][2*jp+1], ah1, wreg.z, wreg.w);
            }
        }
        // stage fp32 results (+bias) into dead K/V regions (pitch 104 floats)
        #pragma unroll
        for (int j = 0; j < 6; j++) {
            int c0 = (g6 * 6 + j) * 8 + (lane & 3) * 2;
            float b0 = __ldg(proj_b + c0), b1 = __ldg(proj_b + c0 + 1);
            #pragma unroll
            for (int w = 0; w < 2; w++) {
                float* stg = (float*)(smc + (w ? WB1 : 0u) + 2 * PLANE);
                *(float2*)(stg + (uint32_t)r0 * 104 + c0) =
                    make_float2(acc[w][j][0] + b0, acc[w][j][1] + b1);
                *(float2*)(stg + (uint32_t)(r0 + 8) * 104 + c0) =
                    make_float2(acc[w][j][2] + b0, acc[w][j][3] + b1);
            }
        }
    }
    __syncthreads();

    // ---- coalesced output copy (both windows) ----
    {
        float4* ob4 = (float4*)(out + (size_t)b2 * 12288);
        #pragma unroll
        for (int i = 0; i < 12; i++) {
            int e4 = t + i * THREADS;            // 3072 float4
            int grow = e4 / 24, c4 = e4 % 24;
            int w = grow >> 6, r = grow & 63;
            const float* stg = (const float*)(smc + (w ? WB1 : 0u) + 2 * PLANE);
            ob4[e4] = *(const float4*)(stg + (uint32_t)r * 104 + c4 * 4);
        }
    }
}

extern "C" void kernel_launch(void* const* d_in, const int* in_sizes, int n_in,
                              void* d_out, int out_size) {
    const float* x      = (const float*)d_in[0];
    const float* mask   = (const float*)d_in[1];
    const float* qkv_w  = (const float*)d_in[2];
    const float* qkv_b  = (const float*)d_in[3];
    const float* proj_w = (const float*)d_in[4];
    const float* proj_b = (const float*)d_in[5];
    const float* rpb    = (const float*)d_in[6];
    const int*   ridx   = (const int*)d_in[7];
    float* out = (float*)d_out;

    const int B_ = in_sizes[0] / (N_TOK * DIM);        // 8192
    const int nW = in_sizes[1] / (N_TOK * N_TOK);      // 512

    int prep_total = 4608 + 6144 + nW * 1024;
    prep_kernel<<<(prep_total + 255) / 256, 256>>>(qkv_w, proj_w, rpb, ridx,
                                                   mask, nW);

    cudaFuncSetAttribute(win_attn_mma,
                         cudaFuncAttributeMaxDynamicSharedMemorySize, SMEM_BYTES);
    win_attn_mma<<<B_ / 2, THREADS, SMEM_BYTES>>>(x, qkv_b, proj_b, out, nW);
}